// round 15
// baseline (speedup 1.0000x reference)
#include <cuda_runtime.h>
#include <cstdint>

// Problem constants (ViT-B/16 @384: b=32, n=577, c=768, H=12, d=64, keep=0.7)
#define B   32
#define N   577
#define C   768
#define HH  12
#define DD  64
#define NK  576
#define FT  404
#define SCALE 0.125f

// Output layout: x | index | ind | class_attention | final_tokens (float32)
#define OFF_X      0ll
#define OFF_INDEX  14180352ll
#define OFF_IND    24109056ll
#define OFF_CA     24121984ll
#define OFF_FT     24140416ll

#define FULLM 0xFFFFFFFFu

// k_dots tiling: 6 c-slices of 128, 5 j-tiles of 128
#define CS   6
#define CSL  128
#define JB   128
#define JT   640

// ---------------- scratch ----------------------------------------------------
__device__ float g_qp[6][B * C];
__device__ float g_q[B * C];
__device__ float g_u[B * HH * C];
__device__ float g_beta[B * HH];
__device__ float g_dotsp[CS * B * HH * JT];
__device__ int   g_ind[B * FT];
__device__ int   g_cnt[B];            // monotonic arrival counters (never reset)

// ---------------- K1: qproj partials + last-block reduce. grid (32,6) -------
__global__ void __launch_bounds__(768) k_qprojp(const float* __restrict__ x,
                                                const float* __restrict__ W,
                                                const float* __restrict__ bqkv) {
    int b = blockIdx.x, s = blockIdx.y, col = threadIdx.x;
    __shared__ float xs[128];
    __shared__ int is_last;
    if (col < 128) xs[col] = x[(size_t)b * N * C + s * 128 + col];
    __syncthreads();
    float acc = 0.f;
#pragma unroll 16
    for (int i = 0; i < 128; i++)
        acc = fmaf(xs[i], W[(size_t)(s * 128 + i) * 3 * C + col], acc);
    g_qp[s][b * C + col] = acc;

    __threadfence();
    __syncthreads();
    if (col == 0) {
        int old = atomicAdd(&g_cnt[b], 1);
        is_last = ((old % 6) == 5);
    }
    __syncthreads();
    if (is_last) {
        float r = bqkv[col];
#pragma unroll
        for (int ss = 0; ss < 6; ss++) r += __ldcg(&g_qp[ss][b * C + col]);
        g_q[b * C + col] = r;
    }
}

// ---------------- K2: u[b,h,c]; beta. grid 192 (4 cc), block 384 ------------
__global__ void k_uproj(const float* __restrict__ W,
                        const float* __restrict__ bqkv) {
    int cc0 = blockIdx.x * 4;
    int tid = threadIdx.x;
    int b = tid / HH, h = tid % HH;

    float q[DD];
    const float4* qp = (const float4*)&g_q[b * C + h * DD];
#pragma unroll
    for (int i = 0; i < DD / 4; i++) {
        float4 v = qp[i];
        q[4 * i + 0] = v.x; q[4 * i + 1] = v.y; q[4 * i + 2] = v.z; q[4 * i + 3] = v.w;
    }

    __shared__ float w[4][C];
#pragma unroll
    for (int s = 0; s < 4; s++) {
        w[s][tid]       = W[(size_t)(cc0 + s) * 3 * C + C + tid];
        w[s][tid + 384] = W[(size_t)(cc0 + s) * 3 * C + C + tid + 384];
    }
    __syncthreads();
#pragma unroll
    for (int s = 0; s < 4; s++) {
        float acc = 0.f;
#pragma unroll
        for (int d = 0; d < DD; d++) acc = fmaf(w[s][h * DD + d], q[d], acc);
        g_u[(size_t)(b * HH + h) * C + cc0 + s] = acc;
    }
    if (blockIdx.x == 0) {
        float acc = 0.f;
#pragma unroll
        for (int d = 0; d < DD; d++) acc = fmaf(bqkv[C + h * DD + d], q[d], acc);
        g_beta[tid] = acc;
    }
}

// ---------------- K3: dots partials. grid (32, CS, 5), block 128 ------------
// Register-direct: thread owns row j, walks its own c-slice float4 by float4.
// No x staging, no transposes, no per-tile barriers. Fused x -> out copy.
__global__ void __launch_bounds__(128) k_dots(const float* __restrict__ x,
                                              float* __restrict__ out) {
    int b = blockIdx.x, cs = blockIdx.y, jt = blockIdx.z, t = threadIdx.x;
    int c0 = cs * CSL;
    int jme = jt * JB + t;

    __shared__ float usT[CSL][12];     // transposed u slice [c][h]
    for (int i = t; i < CSL * HH; i += 128) {
        int h = i / CSL, cc = i % CSL;
        usT[cc][h] = g_u[((size_t)b * HH + h) * C + c0 + cc];
    }
    __syncthreads();

    bool act = (jme < N);
    int jsafe = act ? jme : (N - 1);
    const float4* __restrict__ xr =
        (const float4*)(x + ((size_t)b * N + jsafe) * C + c0);
    float4* __restrict__ orow =
        (float4*)(out + OFF_X + ((size_t)b * N + jsafe) * C + c0);

    float acc[12];
#pragma unroll
    for (int h = 0; h < 12; h++) acc[h] = 0.f;

#pragma unroll 8
    for (int cf = 0; cf < CSL / 4; cf++) {
        float4 xv = xr[cf];
        if (act) orow[cf] = xv;          // fused copy of x
        int cb = cf * 4;
        {
            const float4 u0 = *(const float4*)&usT[cb + 0][0];
            const float4 u1 = *(const float4*)&usT[cb + 0][4];
            const float4 u2 = *(const float4*)&usT[cb + 0][8];
            acc[0]  = fmaf(xv.x, u0.x, acc[0]);  acc[1]  = fmaf(xv.x, u0.y, acc[1]);
            acc[2]  = fmaf(xv.x, u0.z, acc[2]);  acc[3]  = fmaf(xv.x, u0.w, acc[3]);
            acc[4]  = fmaf(xv.x, u1.x, acc[4]);  acc[5]  = fmaf(xv.x, u1.y, acc[5]);
            acc[6]  = fmaf(xv.x, u1.z, acc[6]);  acc[7]  = fmaf(xv.x, u1.w, acc[7]);
            acc[8]  = fmaf(xv.x, u2.x, acc[8]);  acc[9]  = fmaf(xv.x, u2.y, acc[9]);
            acc[10] = fmaf(xv.x, u2.z, acc[10]); acc[11] = fmaf(xv.x, u2.w, acc[11]);
        }
        {
            const float4 u0 = *(const float4*)&usT[cb + 1][0];
            const float4 u1 = *(const float4*)&usT[cb + 1][4];
            const float4 u2 = *(const float4*)&usT[cb + 1][8];
            acc[0]  = fmaf(xv.y, u0.x, acc[0]);  acc[1]  = fmaf(xv.y, u0.y, acc[1]);
            acc[2]  = fmaf(xv.y, u0.z, acc[2]);  acc[3]  = fmaf(xv.y, u0.w, acc[3]);
            acc[4]  = fmaf(xv.y, u1.x, acc[4]);  acc[5]  = fmaf(xv.y, u1.y, acc[5]);
            acc[6]  = fmaf(xv.y, u1.z, acc[6]);  acc[7]  = fmaf(xv.y, u1.w, acc[7]);
            acc[8]  = fmaf(xv.y, u2.x, acc[8]);  acc[9]  = fmaf(xv.y, u2.y, acc[9]);
            acc[10] = fmaf(xv.y, u2.z, acc[10]); acc[11] = fmaf(xv.y, u2.w, acc[11]);
        }
        {
            const float4 u0 = *(const float4*)&usT[cb + 2][0];
            const float4 u1 = *(const float4*)&usT[cb + 2][4];
            const float4 u2 = *(const float4*)&usT[cb + 2][8];
            acc[0]  = fmaf(xv.z, u0.x, acc[0]);  acc[1]  = fmaf(xv.z, u0.y, acc[1]);
            acc[2]  = fmaf(xv.z, u0.z, acc[2]);  acc[3]  = fmaf(xv.z, u0.w, acc[3]);
            acc[4]  = fmaf(xv.z, u1.x, acc[4]);  acc[5]  = fmaf(xv.z, u1.y, acc[5]);
            acc[6]  = fmaf(xv.z, u1.z, acc[6]);  acc[7]  = fmaf(xv.z, u1.w, acc[7]);
            acc[8]  = fmaf(xv.z, u2.x, acc[8]);  acc[9]  = fmaf(xv.z, u2.y, acc[9]);
            acc[10] = fmaf(xv.z, u2.z, acc[10]); acc[11] = fmaf(xv.z, u2.w, acc[11]);
        }
        {
            const float4 u0 = *(const float4*)&usT[cb + 3][0];
            const float4 u1 = *(const float4*)&usT[cb + 3][4];
            const float4 u2 = *(const float4*)&usT[cb + 3][8];
            acc[0]  = fmaf(xv.w, u0.x, acc[0]);  acc[1]  = fmaf(xv.w, u0.y, acc[1]);
            acc[2]  = fmaf(xv.w, u0.z, acc[2]);  acc[3]  = fmaf(xv.w, u0.w, acc[3]);
            acc[4]  = fmaf(xv.w, u1.x, acc[4]);  acc[5]  = fmaf(xv.w, u1.y, acc[5]);
            acc[6]  = fmaf(xv.w, u1.z, acc[6]);  acc[7]  = fmaf(xv.w, u1.w, acc[7]);
            acc[8]  = fmaf(xv.w, u2.x, acc[8]);  acc[9]  = fmaf(xv.w, u2.y, acc[9]);
            acc[10] = fmaf(xv.w, u2.z, acc[10]); acc[11] = fmaf(xv.w, u2.w, acc[11]);
        }
    }

    if (act) {
#pragma unroll
        for (int h = 0; h < 12; h++)
            g_dotsp[((size_t)(cs * B + b) * HH + h) * JT + jme] = acc[h];
    }
}

// ---------------- K4: softmax + head-mean + radix-select top-k + ind --------
// grid 32, block 768 (= 12 heads x 64 threads). Uniform barriers only.
__global__ void __launch_bounds__(768) k_finish(float* __restrict__ out,
                                                const float* __restrict__ keep_rate) {
    int b = blockIdx.x, tid = threadIdx.x;
    int h = tid >> 6, s = tid & 63;
    int lane = tid & 31, warp = tid >> 5;

    __shared__ float redm[24];
    __shared__ float reds[24];
    __shared__ float pr[12][580];
    __shared__ unsigned ovals[NK];
    __shared__ int bins[256];
    __shared__ int wcnt[24];
    __shared__ unsigned sh_pref;
    __shared__ int sh_krem;

    float beta = g_beta[b * HH + h];

    float d[10];
    float m = -1e30f;
#pragma unroll
    for (int k = 0; k < 10; k++) {
        int j = s + 64 * k;
        float v = -1e30f;
        if (j < N) {
            float sum = beta;
#pragma unroll
            for (int cs = 0; cs < CS; cs++)
                sum += g_dotsp[((size_t)(cs * B + b) * HH + h) * JT + j];
            v = SCALE * sum;
        }
        d[k] = v;
        m = fmaxf(m, v);
    }
    for (int o = 16; o; o >>= 1) m = fmaxf(m, __shfl_xor_sync(FULLM, m, o));
    if (lane == 0) redm[warp] = m;
    __syncthreads();
    m = fmaxf(redm[2 * h], redm[2 * h + 1]);

    float e[10];
    float sm = 0.f;
#pragma unroll
    for (int k = 0; k < 10; k++) {
        e[k] = (d[k] > -1e29f) ? __expf(d[k] - m) : 0.f;
        sm += e[k];
    }
    for (int o = 16; o; o >>= 1) sm += __shfl_xor_sync(FULLM, sm, o);
    if (lane == 0) reds[warp] = sm;
    __syncthreads();
    float inv = 1.f / (reds[2 * h] + reds[2 * h + 1]);

#pragma unroll
    for (int k = 0; k < 10; k++) {
        int j = s + 64 * k;
        if (j < N) pr[h][j] = e[k] * inv;
    }
    __syncthreads();

    if (tid < NK) {
        float c = 0.f;
#pragma unroll
        for (int hh = 0; hh < 12; hh++) c += pr[hh][tid + 1];
        c *= (1.f / 12.f);
        out[OFF_CA + (size_t)b * NK + tid] = c;
        unsigned u = __float_as_uint(c);
        ovals[tid] = (u & 0x80000000u) ? ~u : (u | 0x80000000u);
    }
    __syncthreads();

    int K = (int)ceilf(keep_rate[0] * (float)NK);   // 404
    if (tid == 0) sh_krem = K;
    __syncthreads();

    unsigned omine = (tid < NK) ? ovals[tid] : 0u;
#pragma unroll
    for (int pass = 3; pass >= 0; pass--) {
        int shift = pass * 8;
        if (tid < 256) bins[tid] = 0;
        __syncthreads();
        bool cand = (tid < NK) &&
                    (pass == 3 || (omine >> (shift + 8)) == sh_pref);
        if (cand) atomicAdd(&bins[(omine >> shift) & 0xFF], 1);
        __syncthreads();
        if (warp == 0) {
            int cnt[8], sc = 0;
#pragma unroll
            for (int k = 0; k < 8; k++) {
                cnt[k] = bins[255 - (lane * 8 + k)];
                sc += cnt[k];
            }
            int ex = sc;
#pragma unroll
            for (int o2 = 1; o2 < 32; o2 <<= 1) {
                int vsh = __shfl_up_sync(FULLM, ex, o2);
                if (lane >= o2) ex += vsh;
            }
            ex -= sc;
            int krem = sh_krem;
            if (ex < krem && ex + sc >= krem) {
                int run = ex;
#pragma unroll
                for (int k = 0; k < 8; k++) {
                    int dd = 255 - (lane * 8 + k);
                    if (run + cnt[k] >= krem) {
                        sh_krem = krem - run;
                        sh_pref = (pass == 3) ? (unsigned)dd
                                              : ((sh_pref << 8) | (unsigned)dd);
                        break;
                    }
                    run += cnt[k];
                }
            }
        }
        __syncthreads();
    }

    unsigned othr = sh_pref;
    int trem = sh_krem;

    bool sel = false;
    if (tid < NK) {
        if (omine > othr) sel = true;
        else if (omine == othr) {
            int tp = 0;
            for (int j = 0; j < tid; j++) tp += (ovals[j] == othr);
            sel = (tp < trem);
        }
    }
    unsigned mm = __ballot_sync(FULLM, sel);
    if (lane == 0) wcnt[warp] = __popc(mm);
    __syncthreads();
    int base = 0;
    for (int w = 0; w < warp; w++) base += wcnt[w];
    int pos = base + __popc(mm & ((1u << lane) - 1u));
    if (sel) {
        out[OFF_IND + (size_t)b * FT + pos] = (float)tid;
        g_ind[b * FT + pos] = tid;
    }
    if (b == 0 && tid == 0) out[OFF_FT] = (float)K;
}

// ---------------- K5: index broadcast, full-chip ----------------------------
__global__ void k_index(float* __restrict__ out) {
    int t = threadIdx.x;
    int r0 = blockIdx.x * 4;
    float4* op = (float4*)(out + OFF_INDEX) + (size_t)r0 * (C / 4);
#pragma unroll
    for (int k = 0; k < 3; k++) {
        int idx = t + 256 * k;
        int r = idx / (C / 4);
        int col = idx - r * (C / 4);
        float v = (float)g_ind[r0 + r];
        op[(size_t)r * (C / 4) + col] = make_float4(v, v, v, v);
    }
}

// ---------------- launch -----------------------------------------------------
extern "C" void kernel_launch(void* const* d_in, const int* in_sizes, int n_in,
                              void* d_out, int out_size) {
    const float* x    = (const float*)d_in[0];
    const float* kr   = (const float*)d_in[1];
    const float* Wqkv = (const float*)d_in[2];
    const float* bqkv = (const float*)d_in[3];
    float* out = (float*)d_out;

    k_qprojp<<<dim3(B, 6), C>>>(x, Wqkv, bqkv);   // includes q reduce
    k_uproj<<<192, 384>>>(Wqkv, bqkv);
    k_dots<<<dim3(B, CS, 5), 128>>>(x, out);      // includes x -> out copy
    k_finish<<<B, 768>>>(out, kr);
    k_index<<<(B * FT) / 4, 256>>>(out);
}

// round 17
// speedup vs baseline: 1.2424x; 1.2424x over previous
#include <cuda_runtime.h>
#include <cstdint>

// Problem constants (ViT-B/16 @384: b=32, n=577, c=768, H=12, d=64, keep=0.7)
#define B   32
#define N   577
#define C   768
#define HH  12
#define DD  64
#define NK  576
#define FT  404
#define SCALE 0.125f

// Output layout: x | index | ind | class_attention | final_tokens (float32)
#define OFF_X      0ll
#define OFF_INDEX  14180352ll
#define OFF_IND    24109056ll
#define OFF_CA     24121984ll
#define OFF_FT     24140416ll

#define FULLM 0xFFFFFFFFu

// k_dots tiling: 6 c-slices of 128, 5 j-tiles of 128, 32-c cp.async tiles
#define CS   6
#define CSL  128
#define CT   32
#define JB   128
#define JT   640
#define NTILE (CSL / CT)   // 4

// ---------------- scratch ----------------------------------------------------
__device__ float g_qp[6][B * C];
__device__ float g_q[B * C];
__device__ float g_u[B * HH * C];
__device__ float g_beta[B * HH];
__device__ float g_dotsp[CS * B * HH * JT];
__device__ int   g_ind[B * FT];

// ---------------- K1a: qproj partials. grid (32,6), block 768 ---------------
__global__ void __launch_bounds__(768) k_qprojp(const float* __restrict__ x,
                                                const float* __restrict__ W) {
    int b = blockIdx.x, s = blockIdx.y, col = threadIdx.x;
    __shared__ float xs[128];
    if (col < 128) xs[col] = x[(size_t)b * N * C + s * 128 + col];
    __syncthreads();
    float acc = 0.f;
#pragma unroll 16
    for (int i = 0; i < 128; i++)
        acc = fmaf(xs[i], W[(size_t)(s * 128 + i) * 3 * C + col], acc);
    g_qp[s][b * C + col] = acc;
}

// ---------------- K1b: q = sum partials + bias. grid 32, block 768 ----------
__global__ void k_qreduce(const float* __restrict__ bq) {
    int b = blockIdx.x, col = threadIdx.x;
    float acc = bq[col];
#pragma unroll
    for (int s = 0; s < 6; s++) acc += g_qp[s][b * C + col];
    g_q[b * C + col] = acc;
}

// ---------------- K2: u[b,h,c]; beta. grid 192 (4 cc), block 384 ------------
__global__ void k_uproj(const float* __restrict__ W,
                        const float* __restrict__ bqkv) {
    int cc0 = blockIdx.x * 4;
    int tid = threadIdx.x;
    int b = tid / HH, h = tid % HH;

    float q[DD];
    const float4* qp = (const float4*)&g_q[b * C + h * DD];
#pragma unroll
    for (int i = 0; i < DD / 4; i++) {
        float4 v = qp[i];
        q[4 * i + 0] = v.x; q[4 * i + 1] = v.y; q[4 * i + 2] = v.z; q[4 * i + 3] = v.w;
    }

    __shared__ float w[4][C];
#pragma unroll
    for (int s = 0; s < 4; s++) {
        w[s][tid]       = W[(size_t)(cc0 + s) * 3 * C + C + tid];
        w[s][tid + 384] = W[(size_t)(cc0 + s) * 3 * C + C + tid + 384];
    }
    __syncthreads();
#pragma unroll
    for (int s = 0; s < 4; s++) {
        float acc = 0.f;
#pragma unroll
        for (int d = 0; d < DD; d++) acc = fmaf(w[s][h * DD + d], q[d], acc);
        g_u[(size_t)(b * HH + h) * C + cc0 + s] = acc;
    }
    if (blockIdx.x == 0) {
        float acc = 0.f;
#pragma unroll
        for (int d = 0; d < DD; d++) acc = fmaf(bqkv[C + h * DD + d], q[d], acc);
        g_beta[tid] = acc;
    }
}

// ---------------- K3: dots partials. grid (32, CS, 5), block 128 ------------
// cp.async double-buffered, XOR-swizzled smem; fused x->out copy from smem.
__global__ void __launch_bounds__(128) k_dots(const float* __restrict__ x,
                                              float* __restrict__ out) {
    int b = blockIdx.x, cs = blockIdx.y, jt = blockIdx.z, t = threadIdx.x;
    int c0 = cs * CSL;
    int jbase = jt * JB;

    __shared__ float4 xs[2][JB * 8];   // [buf][jr*8 + swizzled_col], 32 KB
    __shared__ float usT[CSL][12];     // 6 KB

    for (int i = t; i < CSL * HH; i += 128) {
        int h = i / CSL, cc = i % CSL;
        usT[cc][h] = g_u[((size_t)b * HH + h) * C + c0 + cc];
    }

    // per-thread chunk coords (8 x 16B per 128j x 32c tile)
    int jr[8], fc[8], sz[8], sw[8];
#pragma unroll
    for (int k = 0; k < 8; k++) {
        int f = t + 128 * k;
        jr[k] = f >> 3; fc[k] = f & 7;
        sw[k] = jr[k] * 8 + (fc[k] ^ (jr[k] & 7));
        sz[k] = (jbase + jr[k] < N) ? 16 : 0;
    }

    const char* srcbase = (const char*)x + (((size_t)b * N + jbase) * C + c0) * 4;
    char* dstbase = (char*)(out + OFF_X) + (((size_t)b * N + jbase) * C + c0) * 4;
    unsigned sbase = (unsigned)__cvta_generic_to_shared(&xs[0][0]);

#define ISSUE_TILE(buf_, ct_) do {                                              \
        _Pragma("unroll")                                                       \
        for (int k = 0; k < 8; k++) {                                           \
            unsigned d = sbase + ((buf_) * (JB * 8) + sw[k]) * 16;              \
            const char* sp = srcbase + (size_t)jr[k] * (C * 4) + (ct_) * 4 + fc[k] * 16; \
            asm volatile("cp.async.ca.shared.global [%0], [%1], 16, %2;\n"      \
                         :: "r"(d), "l"(sp), "r"(sz[k]));                       \
        }                                                                       \
        asm volatile("cp.async.commit_group;\n");                               \
    } while (0)

    float acc[12];
#pragma unroll
    for (int h = 0; h < 12; h++) acc[h] = 0.f;

    ISSUE_TILE(0, 0);

#pragma unroll
    for (int tile = 0; tile < NTILE; tile++) {
        int buf = tile & 1;
        int ct = tile * CT;
        if (tile + 1 < NTILE) {
            ISSUE_TILE((tile + 1) & 1, ct + CT);
            asm volatile("cp.async.wait_group 1;\n");
        } else {
            asm volatile("cp.async.wait_group 0;\n");
        }
        __syncthreads();

        // compute: thread owns row t; 8 float4 along c (swizzled reads, CF)
        int tsw = t & 7;
#pragma unroll
        for (int f2 = 0; f2 < 8; f2++) {
            float4 xv = xs[buf][t * 8 + (f2 ^ tsw)];
            int cb = ct + f2 * 4;
            {
                const float4 u0 = *(const float4*)&usT[cb + 0][0];
                const float4 u1 = *(const float4*)&usT[cb + 0][4];
                const float4 u2 = *(const float4*)&usT[cb + 0][8];
                acc[0]  = fmaf(xv.x, u0.x, acc[0]);  acc[1]  = fmaf(xv.x, u0.y, acc[1]);
                acc[2]  = fmaf(xv.x, u0.z, acc[2]);  acc[3]  = fmaf(xv.x, u0.w, acc[3]);
                acc[4]  = fmaf(xv.x, u1.x, acc[4]);  acc[5]  = fmaf(xv.x, u1.y, acc[5]);
                acc[6]  = fmaf(xv.x, u1.z, acc[6]);  acc[7]  = fmaf(xv.x, u1.w, acc[7]);
                acc[8]  = fmaf(xv.x, u2.x, acc[8]);  acc[9]  = fmaf(xv.x, u2.y, acc[9]);
                acc[10] = fmaf(xv.x, u2.z, acc[10]); acc[11] = fmaf(xv.x, u2.w, acc[11]);
            }
            {
                const float4 u0 = *(const float4*)&usT[cb + 1][0];
                const float4 u1 = *(const float4*)&usT[cb + 1][4];
                const float4 u2 = *(const float4*)&usT[cb + 1][8];
                acc[0]  = fmaf(xv.y, u0.x, acc[0]);  acc[1]  = fmaf(xv.y, u0.y, acc[1]);
                acc[2]  = fmaf(xv.y, u0.z, acc[2]);  acc[3]  = fmaf(xv.y, u0.w, acc[3]);
                acc[4]  = fmaf(xv.y, u1.x, acc[4]);  acc[5]  = fmaf(xv.y, u1.y, acc[5]);
                acc[6]  = fmaf(xv.y, u1.z, acc[6]);  acc[7]  = fmaf(xv.y, u1.w, acc[7]);
                acc[8]  = fmaf(xv.y, u2.x, acc[8]);  acc[9]  = fmaf(xv.y, u2.y, acc[9]);
                acc[10] = fmaf(xv.y, u2.z, acc[10]); acc[11] = fmaf(xv.y, u2.w, acc[11]);
            }
            {
                const float4 u0 = *(const float4*)&usT[cb + 2][0];
                const float4 u1 = *(const float4*)&usT[cb + 2][4];
                const float4 u2 = *(const float4*)&usT[cb + 2][8];
                acc[0]  = fmaf(xv.z, u0.x, acc[0]);  acc[1]  = fmaf(xv.z, u0.y, acc[1]);
                acc[2]  = fmaf(xv.z, u0.z, acc[2]);  acc[3]  = fmaf(xv.z, u0.w, acc[3]);
                acc[4]  = fmaf(xv.z, u1.x, acc[4]);  acc[5]  = fmaf(xv.z, u1.y, acc[5]);
                acc[6]  = fmaf(xv.z, u1.z, acc[6]);  acc[7]  = fmaf(xv.z, u1.w, acc[7]);
                acc[8]  = fmaf(xv.z, u2.x, acc[8]);  acc[9]  = fmaf(xv.z, u2.y, acc[9]);
                acc[10] = fmaf(xv.z, u2.z, acc[10]); acc[11] = fmaf(xv.z, u2.w, acc[11]);
            }
            {
                const float4 u0 = *(const float4*)&usT[cb + 3][0];
                const float4 u1 = *(const float4*)&usT[cb + 3][4];
                const float4 u2 = *(const float4*)&usT[cb + 3][8];
                acc[0]  = fmaf(xv.w, u0.x, acc[0]);  acc[1]  = fmaf(xv.w, u0.y, acc[1]);
                acc[2]  = fmaf(xv.w, u0.z, acc[2]);  acc[3]  = fmaf(xv.w, u0.w, acc[3]);
                acc[4]  = fmaf(xv.w, u1.x, acc[4]);  acc[5]  = fmaf(xv.w, u1.y, acc[5]);
                acc[6]  = fmaf(xv.w, u1.z, acc[6]);  acc[7]  = fmaf(xv.w, u1.w, acc[7]);
                acc[8]  = fmaf(xv.w, u2.x, acc[8]);  acc[9]  = fmaf(xv.w, u2.y, acc[9]);
                acc[10] = fmaf(xv.w, u2.z, acc[10]); acc[11] = fmaf(xv.w, u2.w, acc[11]);
            }
        }

        // fused x -> out copy from smem (chunk coords: 8 lanes = one 128B row)
#pragma unroll
        for (int k = 0; k < 8; k++) {
            if (sz[k]) {
                float4 v = xs[buf][(buf ? JB * 8 : 0) * 0 + sw[k]];   // placeholder avoided below
            }
        }
#pragma unroll
        for (int k = 0; k < 8; k++) {
            if (sz[k]) {
                float4 v = xs[buf][sw[k]];
                *(float4*)(dstbase + (size_t)jr[k] * (C * 4) + ct * 4 + fc[k] * 16) = v;
            }
        }
        __syncthreads();   // protect buffer before reuse by tile+2's issue
    }
#undef ISSUE_TILE

    int jme = jbase + t;
    if (jme < N) {
#pragma unroll
        for (int h = 0; h < 12; h++)
            g_dotsp[((size_t)(cs * B + b) * HH + h) * JT + jme] = acc[h];
    }
}

// ---------------- K4: softmax + head-mean + radix-select top-k + ind --------
// grid 32, block 768 (= 12 heads x 64 threads). Uniform barriers only.
__global__ void __launch_bounds__(768) k_finish(float* __restrict__ out,
                                                const float* __restrict__ keep_rate) {
    int b = blockIdx.x, tid = threadIdx.x;
    int h = tid >> 6, s = tid & 63;
    int lane = tid & 31, warp = tid >> 5;

    __shared__ float redm[24];
    __shared__ float reds[24];
    __shared__ float pr[12][580];
    __shared__ unsigned ovals[NK];
    __shared__ int bins[256];
    __shared__ int wcnt[24];
    __shared__ unsigned sh_pref;
    __shared__ int sh_krem;

    float beta = g_beta[b * HH + h];

    float d[10];
    float m = -1e30f;
#pragma unroll
    for (int k = 0; k < 10; k++) {
        int j = s + 64 * k;
        float v = -1e30f;
        if (j < N) {
            float sum = beta;
#pragma unroll
            for (int cs = 0; cs < CS; cs++)
                sum += g_dotsp[((size_t)(cs * B + b) * HH + h) * JT + j];
            v = SCALE * sum;
        }
        d[k] = v;
        m = fmaxf(m, v);
    }
    for (int o = 16; o; o >>= 1) m = fmaxf(m, __shfl_xor_sync(FULLM, m, o));
    if (lane == 0) redm[warp] = m;
    __syncthreads();
    m = fmaxf(redm[2 * h], redm[2 * h + 1]);

    float e[10];
    float sm = 0.f;
#pragma unroll
    for (int k = 0; k < 10; k++) {
        e[k] = (d[k] > -1e29f) ? __expf(d[k] - m) : 0.f;
        sm += e[k];
    }
    for (int o = 16; o; o >>= 1) sm += __shfl_xor_sync(FULLM, sm, o);
    if (lane == 0) reds[warp] = sm;
    __syncthreads();
    float inv = 1.f / (reds[2 * h] + reds[2 * h + 1]);

#pragma unroll
    for (int k = 0; k < 10; k++) {
        int j = s + 64 * k;
        if (j < N) pr[h][j] = e[k] * inv;
    }
    __syncthreads();

    if (tid < NK) {
        float c = 0.f;
#pragma unroll
        for (int hh = 0; hh < 12; hh++) c += pr[hh][tid + 1];
        c *= (1.f / 12.f);
        out[OFF_CA + (size_t)b * NK + tid] = c;
        unsigned u = __float_as_uint(c);
        ovals[tid] = (u & 0x80000000u) ? ~u : (u | 0x80000000u);
    }
    __syncthreads();

    int K = (int)ceilf(keep_rate[0] * (float)NK);   // 404
    if (tid == 0) sh_krem = K;
    __syncthreads();

    unsigned omine = (tid < NK) ? ovals[tid] : 0u;
#pragma unroll
    for (int pass = 3; pass >= 0; pass--) {
        int shift = pass * 8;
        if (tid < 256) bins[tid] = 0;
        __syncthreads();
        bool cand = (tid < NK) &&
                    (pass == 3 || (omine >> (shift + 8)) == sh_pref);
        if (cand) atomicAdd(&bins[(omine >> shift) & 0xFF], 1);
        __syncthreads();
        if (warp == 0) {
            int cnt[8], sc = 0;
#pragma unroll
            for (int k = 0; k < 8; k++) {
                cnt[k] = bins[255 - (lane * 8 + k)];
                sc += cnt[k];
            }
            int ex = sc;
#pragma unroll
            for (int o2 = 1; o2 < 32; o2 <<= 1) {
                int vsh = __shfl_up_sync(FULLM, ex, o2);
                if (lane >= o2) ex += vsh;
            }
            ex -= sc;
            int krem = sh_krem;
            if (ex < krem && ex + sc >= krem) {
                int run = ex;
#pragma unroll
                for (int k = 0; k < 8; k++) {
                    int dd = 255 - (lane * 8 + k);
                    if (run + cnt[k] >= krem) {
                        sh_krem = krem - run;
                        sh_pref = (pass == 3) ? (unsigned)dd
                                              : ((sh_pref << 8) | (unsigned)dd);
                        break;
                    }
                    run += cnt[k];
                }
            }
        }
        __syncthreads();
    }

    unsigned othr = sh_pref;
    int trem = sh_krem;

    bool sel = false;
    if (tid < NK) {
        if (omine > othr) sel = true;
        else if (omine == othr) {
            int tp = 0;
            for (int j = 0; j < tid; j++) tp += (ovals[j] == othr);
            sel = (tp < trem);
        }
    }
    unsigned mm = __ballot_sync(FULLM, sel);
    if (lane == 0) wcnt[warp] = __popc(mm);
    __syncthreads();
    int base = 0;
    for (int w = 0; w < warp; w++) base += wcnt[w];
    int pos = base + __popc(mm & ((1u << lane) - 1u));
    if (sel) {
        out[OFF_IND + (size_t)b * FT + pos] = (float)tid;
        g_ind[b * FT + pos] = tid;
    }
    if (b == 0 && tid == 0) out[OFF_FT] = (float)K;
}

// ---------------- K5: index broadcast, full-chip ----------------------------
__global__ void k_index(float* __restrict__ out) {
    int t = threadIdx.x;
    int r0 = blockIdx.x * 4;
    float4* op = (float4*)(out + OFF_INDEX) + (size_t)r0 * (C / 4);
#pragma unroll
    for (int k = 0; k < 3; k++) {
        int idx = t + 256 * k;
        int r = idx / (C / 4);
        int col = idx - r * (C / 4);
        float v = (float)g_ind[r0 + r];
        op[(size_t)r * (C / 4) + col] = make_float4(v, v, v, v);
    }
}

// ---------------- launch -----------------------------------------------------
extern "C" void kernel_launch(void* const* d_in, const int* in_sizes, int n_in,
                              void* d_out, int out_size) {
    const float* x    = (const float*)d_in[0];
    const float* kr   = (const float*)d_in[1];
    const float* Wqkv = (const float*)d_in[2];
    const float* bqkv = (const float*)d_in[3];
    float* out = (float*)d_out;

    k_qprojp<<<dim3(B, 6), C>>>(x, Wqkv);
    k_qreduce<<<B, C>>>(bqkv);
    k_uproj<<<192, 384>>>(Wqkv, bqkv);
    k_dots<<<dim3(B, CS, 5), 128>>>(x, out);   // also copies x -> out
    k_finish<<<B, 768>>>(out, kr);
    k_index<<<(B * FT) / 4, 256>>>(out);
}